// round 3
// baseline (speedup 1.0000x reference)
#include <cuda_runtime.h>
#include <math.h>

#define NEGV (-1e30f)

// B=8, S=512, L=32, M=64
#define B_ 8
#define S_ 512
#define L_ 32
#define M_ 64

// scratch[b][e][cur][jm1] = segment_score[b][e-jm1][e][cur]
__device__ float g_scratch[B_ * S_ * L_ * M_];   // 32 MB

__device__ __forceinline__ float redux_max_f32(float x) {
    unsigned u = __float_as_uint(x);
    u = (u & 0x80000000u) ? ~u : (u | 0x80000000u);   // monotone key
    unsigned r = __reduce_max_sync(0xffffffffu, u);
    return (r & 0x80000000u) ? __uint_as_float(r ^ 0x80000000u)
                             : __uint_as_float(~r);
}
__device__ __forceinline__ float warp_sum(float v) {
#pragma unroll
    for (int o = 16; o; o >>= 1) v += __shfl_xor_sync(0xffffffffu, v, o);
    return v;
}

// -------- pre-pass: gather band into contiguous [b][e][cur][jm1] layout --------
__global__ void transpose_kernel(const float* __restrict__ seg) {
    int be = blockIdx.x;
    int b = be >> 9;
    int e = be & (S_ - 1);
    __shared__ float tile[L_][M_ + 1];
    int tid = threadIdx.x;
    for (int idx = tid; idx < M_ * L_; idx += 256) {
        int jm1 = idx >> 5;
        int c   = idx & 31;
        float v = 0.0f;
        int s = e - jm1;
        if (s >= 0) v = seg[(((size_t)b * S_ + s) * S_ + e) * L_ + c];
        tile[c][jm1] = v;
    }
    __syncthreads();
    float* out = &g_scratch[((size_t)(b * S_ + e)) * (L_ * M_)];
    for (int idx = tid; idx < L_ * M_; idx += 256) {
        int c   = idx >> 6;
        int jm1 = idx & 63;
        out[idx] = tile[c][jm1];
    }
}

// -------- sequential recurrence: one CTA per batch, warp = cur label --------
__global__ __launch_bounds__(1024, 1) void crf_kernel(const float* __restrict__ trans,
                                                      float* __restrict__ out) {
    __shared__ float2 s_alpha[2][L_];     // (m, s) pairs, double buffered
    __shared__ float  s_beta[M_ * 33];    // ring of normalized beta values

    const int b    = blockIdx.x;
    const int tid  = threadIdx.x;
    const int cur  = tid >> 5;
    const int lane = tid & 31;

    const float treg = trans[lane * L_ + cur];   // T[prev=lane][cur]
    const float diag = trans[cur * L_ + cur];
    const float* seg_base = &g_scratch[((size_t)(b * S_)) * (L_ * M_)];

    for (int i = tid; i < M_ * 33; i += 1024) s_beta[i] = NEGV;
    if (tid < L_) s_alpha[0][tid] = make_float2(seg_base[tid * M_], 1.0f);

    // per-lane segment-length constants: slot a -> j=lane+2, slot b -> j=lane+34
    const float fja = (float)(lane + 2), fjb = (float)(lane + 34);
    const float da  = diag * (float)(lane + 1);
    const float db  = diag * (float)(lane + 33);

    // frame-1 bundle + rest[1] (only the init segment [0,1] is valid)
    float s0_cur, Rm, Rs;
    {
        const float* r1 = seg_base + (size_t)(1 * L_ + cur) * M_;
        s0_cur = r1[0];
        float i1 = r1[1];
        float tb = (lane == 31) ? (i1 * 2.0f + diag) : NEGV;
        Rm = redux_max_f32(tb);
        Rs = warp_sum(__expf(tb - Rm));   // exp(-1e30 - Rm) == 0 for inactive lanes
    }
    // frame-2 bundle
    float nsa, nsb, ns0, ninit;
    {
        const float* r2 = seg_base + (size_t)(2 * L_ + cur) * M_;
        nsa = r2[lane + 1];
        nsb = (lane < 31) ? r2[lane + 33] : 0.0f;
        ns0 = r2[0];
        ninit = r2[2];
    }
    __syncthreads();

    for (int f = 1; f < S_; ++f) {
        // prefetch frame f+2 bundle (used two roles ahead)
        float psa = 0.f, psb = 0.f, ps0 = 0.f, pinit = 0.f;
        if (f + 2 < S_) {
            const float* r = seg_base + (size_t)((f + 2) * L_ + cur) * M_;
            psa = r[lane + 1];
            psb = (lane < 31) ? r[lane + 33] : 0.0f;
            ps0 = r[0];
            if (f + 2 < M_) pinit = r[f + 2];
        }

        // ---- beta[f-1][cur] = LSE_prev( alpha[f-1][prev] + T[prev][cur] ) ----
        float2 ap = s_alpha[(f - 1) & 1][lane];
        float Bm = redux_max_f32(ap.x);                       // exact max of pair-m
        float Bs = warp_sum(ap.y * __expf(ap.x + treg - Bm)); // args <= +1, safe
        float beta = Bm + __logf(Bs);                         // normalized

        // ---- alpha[f] = LSE( rest[f], beta[f-1] + seg(f,f) ) as (m,s) pair ----
        float t1 = beta + s0_cur;            // j=1: seg*1, diag*(j-1)=0
        float Am = fmaxf(Rm, t1);
        float eo = __expf(fminf(Rm, t1) - Am);
        float As = (Rm >= t1) ? (Rs + eo) : (Rs * eo + 1.0f);

        if (lane == 0) {
            s_alpha[f & 1][cur] = make_float2(Am, As);
            s_beta[((f - 1) & 63) * 33 + cur] = beta;
        }
        __syncthreads();

        // ---- rest[f+1]: LSE over j=2..64 (+ init) for frame g=f+1 ----
        int sla = (f - 1 - lane) & 63;    // g - (lane+2)
        int slb = (f - 33 - lane) & 63;   // g - (lane+34)
        float ba = (lane == 0) ? beta : s_beta[sla * 33 + cur];
        float ta = ba + nsa * fja + da;
        float tb;
        if (lane < 31) tb = s_beta[slb * 33 + cur] + nsb * fjb + db;
        else           tb = (f + 1 < M_) ? (ninit * (float)(f + 2) + diag * (float)(f + 1))
                                         : NEGV;
        float m2 = redux_max_f32(fmaxf(ta, tb));
        Rs = warp_sum(__expf(ta - m2) + __expf(tb - m2));
        Rm = m2;

        s0_cur = ns0; nsa = psa; nsb = psb; ns0 = ps0; ninit = pinit;
    }

    // ---- log_z = LSE_cur alpha[S-1][cur] ----
    if (cur == 0) {
        float2 p = s_alpha[(S_ - 1) & 1][lane];
        float v = p.x + __logf(p.y);
        float m = redux_max_f32(v);
        float s = warp_sum(__expf(v - m));
        if (lane == 0) out[b] = m + __logf(s);
    }
}

extern "C" void kernel_launch(void* const* d_in, const int* in_sizes, int n_in,
                              void* d_out, int out_size) {
    const float* seg   = (const float*)d_in[0];
    const float* trans = (const float*)d_in[1];
    if (n_in >= 2 && in_sizes[0] == L_ * L_) {
        trans = (const float*)d_in[0];
        seg   = (const float*)d_in[1];
    }
    float* out = (float*)d_out;

    transpose_kernel<<<B_ * S_, 256>>>(seg);
    crf_kernel<<<B_, 1024>>>(trans, out);
}

// round 4
// speedup vs baseline: 1.1534x; 1.1534x over previous
#include <cuda_runtime.h>
#include <math.h>

#define NEGV (-1e30f)

// B=8, S=512, L=32, M=64
#define B_ 8
#define S_ 512
#define L_ 32
#define M_ 64
#define SP_ (S_ + 2)          // padded frames so prefetch needs no bounds check
#define LOG2E_ 1.4426950408889634f
#define LN2_   0.6931471805599453f

// scratch[b][e][cur][jm1] = segment_score[b][e-jm1][e][cur] * LOG2E   (log2 domain)
__device__ float g_scratch[B_ * SP_ * L_ * M_];   // ~32 MB

__device__ __forceinline__ float redux_max_f32(float x) {
    unsigned u = __float_as_uint(x);
    u = (u & 0x80000000u) ? ~u : (u | 0x80000000u);   // monotone key
    unsigned r = __reduce_max_sync(0xffffffffu, u);
    return (r & 0x80000000u) ? __uint_as_float(r ^ 0x80000000u)
                             : __uint_as_float(~r);
}

// log2-sum-exp tail: given terms t (per lane) and exact/near max m (all lanes),
// returns m + log2(sum_lanes 2^(t-m)) using u32 fixed-point redux.
__device__ __forceinline__ float lse2_tail(float expo_sum_u_as_f, float m) {
    return m + (__log2f(expo_sum_u_as_f) - 24.0f);
}

// -------- pre-pass: gather band into contiguous [b][e][cur][jm1] layout, scaled --------
__global__ void transpose_kernel(const float* __restrict__ seg) {
    int be = blockIdx.x;
    int b = be >> 9;
    int e = be & (S_ - 1);
    __shared__ float tile[L_][M_ + 1];
    int tid = threadIdx.x;
    for (int idx = tid; idx < M_ * L_; idx += 256) {
        int jm1 = idx >> 5;
        int c   = idx & 31;
        float v = 0.0f;
        int s = e - jm1;
        if (s >= 0) v = seg[(((size_t)b * S_ + s) * S_ + e) * L_ + c] * LOG2E_;
        tile[c][jm1] = v;
    }
    __syncthreads();
    float* out = &g_scratch[((size_t)(b * SP_ + e)) * (L_ * M_)];
    for (int idx = tid; idx < L_ * M_; idx += 256) {
        int c   = idx >> 6;
        int jm1 = idx & 63;
        out[idx] = tile[c][jm1];
    }
}

// -------- sequential recurrence: one CTA per batch, warp = cur label --------
__global__ __launch_bounds__(1024, 1) void crf_kernel(const float* __restrict__ trans,
                                                      float* __restrict__ out) {
    __shared__ float s_alpha[2][L_];      // scalar log2-alpha, double buffered
    __shared__ float s_beta[M_ * 33];     // ring of log2-beta

    const int b    = blockIdx.x;
    const int tid  = threadIdx.x;
    const int cur  = tid >> 5;
    const int lane = tid & 31;

    const float treg = trans[lane * L_ + cur] * LOG2E_;   // T[prev=lane][cur], log2 domain
    const float diag = trans[cur * L_ + cur] * LOG2E_;
    const float* seg_base = &g_scratch[((size_t)(b * SP_)) * (L_ * M_)];

    for (int i = tid; i < M_ * 33; i += 1024) s_beta[i] = NEGV;
    if (tid < L_) s_alpha[0][tid] = seg_base[tid * M_];   // alpha[0][c] = seg(0,0,c)

    // per-lane segment-length constants: slot a -> j=lane+2, slot b -> j=lane+34
    const float fja = (float)(lane + 2), fjb = (float)(lane + 34);
    const float da  = diag * (float)(lane + 1);
    const float db  = diag * (float)(lane + 33);

    // frame-1 bundle; Rest[1] = init segment [0,1] only (length 2)
    float s0_cur, RestL;
    {
        const float* r1 = seg_base + (size_t)(1 * L_ + cur) * M_;
        s0_cur = r1[0];
        RestL  = r1[1] * 2.0f + diag;
    }
    // frame-2 bundle
    float nsa, nsb, ns0, ninit;
    {
        const float* r2 = seg_base + (size_t)(2 * L_ + cur) * M_;
        nsa = r2[lane + 1];
        nsb = (lane < 31) ? r2[lane + 33] : 0.0f;
        ns0 = r2[0];
        ninit = r2[2];
    }
    __syncthreads();

    for (int f = 1; f < S_; ++f) {
        // prefetch frame f+2 bundle (padded scratch: no bounds check on frame)
        const float* r = seg_base + (size_t)((f + 2) * L_ + cur) * M_;
        float psa = r[lane + 1];
        float psb = (lane < 31) ? r[lane + 33] : 0.0f;
        float ps0 = r[0];
        float pinit = (f + 2 < M_) ? r[f + 2] : 0.0f;

        // ---- beta[f-1][cur] = LSE2_prev( alpha[f-1][prev] + T[prev][cur] ) ----
        float ap = s_alpha[(f - 1) & 1][lane];
        float Bm = redux_max_f32(ap);                       // within |T|<=1.45 of true max
        unsigned bu = (unsigned)exp2f(ap + treg - Bm + 24.0f);
        unsigned bs = __reduce_add_sync(0xffffffffu, bu);
        float beta = Bm + (__log2f((float)bs) - 24.0f);     // all lanes hold it

        // ---- alpha[f] = log2-add( Rest[f], beta + seg(f,f) ) ----
        float t1 = beta + s0_cur;                           // j=1 term
        float Am = fmaxf(RestL, t1);
        float alpha_new = Am + __log2f(exp2f(fminf(RestL, t1) - Am) + 1.0f);

        if (lane == 0) {
            s_alpha[f & 1][cur] = alpha_new;
            s_beta[((f - 1) & 63) * 33 + cur] = beta;
        }
        __syncthreads();

        // ---- Rest[f+1]: LSE2 over j=2..64 (+ init) for frame g=f+1 ----
        int sla = (f - 1 - lane) & 63;    // g - (lane+2)
        int slb = (f - 33 - lane) & 63;   // g - (lane+34)
        float ba = (lane == 0) ? beta : s_beta[sla * 33 + cur];
        float ta = ba + nsa * fja + da;
        float tb;
        if (lane < 31) tb = s_beta[slb * 33 + cur] + nsb * fjb + db;
        else           tb = (f + 1 < M_) ? (ninit * (float)(f + 2) + diag * (float)(f + 1))
                                         : NEGV;
        float m2 = redux_max_f32(fmaxf(ta, tb));
        unsigned ru = (unsigned)exp2f(ta - m2 + 24.0f) + (unsigned)exp2f(tb - m2 + 24.0f);
        unsigned rs = __reduce_add_sync(0xffffffffu, ru);
        RestL = m2 + (__log2f((float)rs) - 24.0f);

        s0_cur = ns0; nsa = psa; nsb = psb; ns0 = ps0; ninit = pinit;
    }

    // ---- log_z = LN2 * LSE2_cur alpha[S-1][cur] ----
    if (cur == 0) {
        float v = s_alpha[(S_ - 1) & 1][lane];
        float m = redux_max_f32(v);
        unsigned u = (unsigned)exp2f(v - m + 24.0f);
        unsigned s = __reduce_add_sync(0xffffffffu, u);
        if (lane == 0) out[b] = (m + (__log2f((float)s) - 24.0f)) * LN2_;
    }
}

extern "C" void kernel_launch(void* const* d_in, const int* in_sizes, int n_in,
                              void* d_out, int out_size) {
    const float* seg   = (const float*)d_in[0];
    const float* trans = (const float*)d_in[1];
    if (n_in >= 2 && in_sizes[0] == L_ * L_) {
        trans = (const float*)d_in[0];
        seg   = (const float*)d_in[1];
    }
    float* out = (float*)d_out;

    transpose_kernel<<<B_ * S_, 256>>>(seg);
    crf_kernel<<<B_, 1024>>>(trans, out);
}

// round 6
// speedup vs baseline: 1.6497x; 1.4303x over previous
#include <cuda_runtime.h>
#include <math.h>

#define NEGV (-1e30f)

// B=8, S=512, L=32, M=64
#define B_ 8
#define S_ 512
#define L_ 32
#define M_ 64
#define SP_ (S_ + 2)          // padded frames: prefetch never needs a bounds check
#define LOG2E_ 1.4426950408889634f
#define LN2_   0.6931471805599453f

// scratch[b][e][cur][jm1] = segment_score[b][e-jm1][e][cur] * LOG2E   (log2 domain)
__device__ float g_scratch[B_ * SP_ * L_ * M_];   // ~32 MB

__device__ __forceinline__ float ex2f(float x) {
    float y; asm("ex2.approx.ftz.f32 %0, %1;" : "=f"(y) : "f"(x)); return y;
}
__device__ __forceinline__ float lg2f(float x) {
    float y; asm("lg2.approx.ftz.f32 %0, %1;" : "=f"(y) : "f"(x)); return y;
}

__device__ __forceinline__ float redux_max_f32(float x) {
    unsigned u = __float_as_uint(x);
    unsigned k = u ^ (((unsigned)((int)u >> 31)) | 0x80000000u);      // monotone key
    unsigned r = __reduce_max_sync(0xffffffffu, k);
    return __uint_as_float(r ^ ((~((unsigned)((int)r >> 31))) | 0x80000000u));
}

// -------- pre-pass: gather band into contiguous [b][e][cur][jm1] layout, log2-scaled --------
__global__ void transpose_kernel(const float* __restrict__ seg) {
    int be = blockIdx.x;
    int b = be >> 9;
    int e = be & (S_ - 1);
    __shared__ float tile[L_][M_ + 1];
    int tid = threadIdx.x;
    for (int idx = tid; idx < M_ * L_; idx += 256) {
        int jm1 = idx >> 5;
        int c   = idx & 31;
        float v = 0.0f;
        int s = e - jm1;
        if (s >= 0) v = seg[(((size_t)b * S_ + s) * S_ + e) * L_ + c] * LOG2E_;
        tile[c][jm1] = v;
    }
    __syncthreads();
    float* out = &g_scratch[((size_t)(b * SP_ + e)) * (L_ * M_)];
    for (int idx = tid; idx < L_ * M_; idx += 256) {
        int c   = idx >> 6;
        int jm1 = idx & 63;
        out[idx] = tile[c][jm1];
    }
}

// -------- sequential recurrence: one CTA per batch, warp = cur label --------
// Alpha kept as unnormalized (m, s) pair with s in [1, ~3): log2-alpha = m + log2(s).
// Beta reductions done in u32 fixed point (bias 2^23), Rest in u32 (bias 2^24) then
// renormalized via exponent-field bit surgery (no MUFU).
__global__ __launch_bounds__(1024, 1) void crf_kernel(const float* __restrict__ trans,
                                                      float* __restrict__ out) {
    __shared__ float2 s_alpha[2][L_];
    __shared__ float  s_beta[M_ * 33];

    const int b    = blockIdx.x;
    const int tid  = threadIdx.x;
    const int cur  = tid >> 5;
    const int lane = tid & 31;
    const bool lane0  = (lane == 0);
    const bool lane31 = (lane == 31);

    const float treg23 = trans[lane * L_ + cur] * LOG2E_ + 23.0f;  // T[prev=lane][cur] + bias
    const float diag   = trans[cur * L_ + cur] * LOG2E_;
    const float* seg_base = &g_scratch[((size_t)(b * SP_)) * (L_ * M_)];

    for (int i = tid; i < M_ * 33; i += 1024) s_beta[i] = NEGV;
    if (tid < L_) s_alpha[0][tid] = make_float2(seg_base[tid * M_], 1.0f);

    const float fja = (float)(lane + 2), fjb = (float)(lane + 34);
    const float da  = diag * (float)(lane + 1);
    const float db  = diag * (float)(lane + 33);

    // frame-1 bundle; Rest[1] = init segment [0,1] only (length 2), as normalized pair
    float s0_cur, Rm, Rs;
    {
        const float* r1 = seg_base + (size_t)(1 * L_ + cur) * M_;
        s0_cur = r1[0];
        Rm = r1[1] * 2.0f + diag;
        Rs = 1.0f;
    }
    // frame-2 bundle
    float nsa, nsb, ns0, ninit;
    {
        const float* r2 = seg_base + (size_t)(2 * L_ + cur) * M_;
        nsa = r2[lane + 1];
        nsb = lane31 ? 0.0f : r2[lane + 33];
        ns0 = r2[0];
        ninit = r2[2];
    }
    __syncthreads();

    const float* pref = seg_base + (size_t)(3 * L_ + cur) * M_;   // row for frame f+2 at f=1

#define STEP_BODY(PH1)                                                               \
    {                                                                                \
        /* prefetch frame f+2 bundle */                                              \
        float psa = pref[lane + 1];                                                  \
        float psb = lane31 ? 0.0f : pref[lane + 33];                                 \
        float ps0 = pref[0];                                                         \
        float pinit = 0.0f;                                                          \
        if (PH1) { if (f + 2 < M_) pinit = pref[f + 2]; }                            \
        pref += L_ * M_;                                                             \
                                                                                     \
        /* beta[f-1][cur] = LSE2_prev( alpha-pair + T ) */                           \
        float2 ap = s_alpha[(f - 1) & 1][lane];                                      \
        float Bm = redux_max_f32(ap.x);                                              \
        unsigned bu = (unsigned)(ap.y * ex2f(ap.x + treg23 - Bm));                   \
        unsigned bsum = __reduce_add_sync(0xffffffffu, bu);                          \
        float beta = (Bm - 23.0f) + lg2f((float)bsum);                               \
                                                                                     \
        /* alpha[f] pair = combine(Rest[f], beta + seg(f,f)) */                      \
        float t1 = beta + s0_cur;                                                    \
        float Am = fmaxf(Rm, t1);                                                    \
        float d  = Rm - t1;                                                          \
        float e  = ex2f(0.0f - fabsf(d));                                            \
        float As = (d >= 0.0f) ? (Rs + e) : fmaf(Rs, e, 1.0f);                       \
                                                                                     \
        if (lane0) {                                                                 \
            s_alpha[f & 1][cur] = make_float2(Am, As);                               \
            s_beta[((f - 1) & 63) * 33 + cur] = beta;                                \
        }                                                                            \
        __syncthreads();                                                             \
                                                                                     \
        /* Rest[f+1]: j=2..64 (+ init in phase 1) */                                 \
        int sla = ((f - 1 - lane) & 63) * 33 + cur;                                  \
        int slb = ((f - 33 - lane) & 63) * 33 + cur;                                 \
        float ba = lane0 ? beta : s_beta[sla];                                       \
        float ta = fmaf(nsa, fja, da) + ba;                                          \
        float tb;                                                                    \
        if (PH1) {                                                                   \
            tb = lane31 ? ((f + 1 < M_)                                              \
                             ? fmaf(ninit, (float)(f + 2), diag * (float)(f + 1))    \
                             : NEGV)                                                 \
                        : s_beta[slb] + fmaf(nsb, fjb, db);                          \
        } else {                                                                     \
            tb = lane31 ? NEGV : s_beta[slb] + fmaf(nsb, fjb, db);                   \
        }                                                                            \
        float m2 = redux_max_f32(fmaxf(ta, tb));                                     \
        float m24 = m2 - 24.0f;                                                      \
        unsigned ru = (unsigned)ex2f(ta - m24) + (unsigned)ex2f(tb - m24);           \
        unsigned rsum = __reduce_add_sync(0xffffffffu, ru);                          \
        /* normalized Rest pair via exponent bit surgery */                          \
        float rsf = (float)rsum;                                                     \
        unsigned rb = __float_as_uint(rsf);                                          \
        int li = (int)(rb >> 23) - 127;                                              \
        Rm = m24 + (float)li;                                                        \
        Rs = __uint_as_float(rb - ((unsigned)li << 23));                             \
                                                                                     \
        s0_cur = ns0; nsa = psa; nsb = psb; ns0 = ps0; ninit = pinit;                \
    }

    for (int f = 1; f <= 62; ++f) STEP_BODY(true)
    for (int f = 63; f < S_; ++f) STEP_BODY(false)
#undef STEP_BODY

    // ---- log_z = LN2 * LSE2_cur ( alpha[S-1] pair ) ----
    if (cur == 0) {
        float2 p = s_alpha[(S_ - 1) & 1][lane];
        float v = p.x + lg2f(p.y);
        float m = redux_max_f32(v);
        unsigned u = (unsigned)ex2f(v - m + 24.0f);
        unsigned s = __reduce_add_sync(0xffffffffu, u);
        if (lane == 0) out[b] = (m - 24.0f + lg2f((float)s)) * LN2_;
    }
}

extern "C" void kernel_launch(void* const* d_in, const int* in_sizes, int n_in,
                              void* d_out, int out_size) {
    const float* seg   = (const float*)d_in[0];
    const float* trans = (const float*)d_in[1];
    if (n_in >= 2 && in_sizes[0] == L_ * L_) {
        trans = (const float*)d_in[0];
        seg   = (const float*)d_in[1];
    }
    float* out = (float*)d_out;

    transpose_kernel<<<B_ * S_, 256>>>(seg);
    crf_kernel<<<B_, 1024>>>(trans, out);
}